// round 3
// baseline (speedup 1.0000x reference)
#include <cuda_runtime.h>
#include <cstdint>

// Problem constants (DeformConvPack_39187281609181)
#define B_   4
#define C_   64
#define H_   128
#define W_   256
#define HW_  (H_ * W_)      // 32768
#define COUT 64
#define COB  32             // Cout per block (split in 2)
#define KK   9              // 3x3
#define HO   128
#define WO   256
#define NPIX (B_ * HO * WO) // 131072

#define THREADS 256
#define SMEM_W_FLOATS (KK * C_ * COB)      // 18432
#define SMEM_BYTES    (SMEM_W_FLOATS * 4)  // 73728

__global__ void __launch_bounds__(THREADS, 3)
deform_conv_kernel(const float* __restrict__ x,
                   const float* __restrict__ offset,
                   const float* __restrict__ weight,
                   const float* __restrict__ bias,
                   float* __restrict__ out)
{
    extern __shared__ float w_s[];   // layout: [(k*64 + c)*32 + oc_local]

    const int tid     = threadIdx.x;
    const int oc_base = blockIdx.y * COB;   // 0 or 32

    // ---- Stage this block's half of the weights into smem, transposed ----
    // src: weight[(oc_base+oc)*576 + c*9 + k] ; dst t = (k*64+c)*32 + oc
    for (int t = tid; t < SMEM_W_FLOATS; t += THREADS) {
        int oc = t & 31;
        int ck = t >> 5;        // k*64 + c
        int k  = ck >> 6;       // 0..8
        int c  = ck & 63;
        w_s[t] = __ldg(weight + (size_t)(oc_base + oc) * (C_ * KK) + c * KK + k);
    }

    // ---- Accumulators: 16 packed f32x2 covering oc_local = (2i, 2i+1) ----
    unsigned long long acc[16];
    {
        const float2* b2 = reinterpret_cast<const float2*>(bias + oc_base);
        #pragma unroll
        for (int i = 0; i < 16; ++i) {
            float2 t = __ldg(b2 + i);
            asm("mov.b64 %0, {%1, %2};" : "=l"(acc[i]) : "f"(t.x), "f"(t.y));
        }
    }

    __syncthreads();

    // ---- Pixel assignment ----
    const int p  = blockIdx.x * THREADS + tid;   // 0..131071
    const int b  = p >> 15;                      // / (HO*WO)
    const int hw = p & 32767;
    const int ho = hw >> 8;                      // / WO
    const int wo = hw & 255;

    const float* xb = x + (size_t)b * C_ * HW_;

    #pragma unroll 1
    for (int k = 0; k < KK; ++k) {
        const int ky = k / 3;
        const int kx = k - 3 * ky;

        // offsets: (B, 2K, Ho, Wo), dy = chan 2k, dx = chan 2k+1
        const size_t obase = (((size_t)b * (2 * KK) + 2 * k) * HO + ho) * WO + wo;
        const float dy = __ldg(offset + obase);
        const float dx = __ldg(offset + obase + (size_t)HO * WO);

        const float py = (float)(ho - 1 + ky) + dy;
        const float px = (float)(wo - 1 + kx) + dx;

        const float y0f = floorf(py);
        const float x0f = floorf(px);
        const float ly = py - y0f;
        const float lx = px - x0f;

        const int y0 = (int)y0f;
        const int x0 = (int)x0f;
        const int y1 = y0 + 1;
        const int x1 = x0 + 1;

        const float vy0 = (y0 >= 0 && y0 < H_) ? 1.0f : 0.0f;
        const float vy1 = (y1 >= 0 && y1 < H_) ? 1.0f : 0.0f;
        const float vx0 = (x0 >= 0 && x0 < W_) ? 1.0f : 0.0f;
        const float vx1 = (x1 >= 0 && x1 < W_) ? 1.0f : 0.0f;

        const float w00 = (1.0f - ly) * (1.0f - lx) * vy0 * vx0;
        const float w01 = (1.0f - ly) * lx          * vy0 * vx1;
        const float w10 = ly          * (1.0f - lx) * vy1 * vx0;
        const float w11 = ly          * lx          * vy1 * vx1;

        const int y0c = min(max(y0, 0), H_ - 1);
        const int y1c = min(max(y1, 0), H_ - 1);
        const int x0c = min(max(x0, 0), W_ - 1);
        const int x1c = min(max(x1, 0), W_ - 1);

        const int s00 = y0c * W_ + x0c;
        const int s01 = y0c * W_ + x1c;
        const int s10 = y1c * W_ + x0c;
        const int s11 = y1c * W_ + x1c;

        const ulonglong2* wk =
            reinterpret_cast<const ulonglong2*>(w_s + k * (C_ * COB));

        #pragma unroll 4
        for (int c = 0; c < C_; ++c) {
            const float* xc = xb + (size_t)c * HW_;
            const float v00 = __ldg(xc + s00);
            const float v01 = __ldg(xc + s01);
            const float v10 = __ldg(xc + s10);
            const float v11 = __ldg(xc + s11);

            float val = w00 * v00;
            val = fmaf(w01, v01, val);
            val = fmaf(w10, v10, val);
            val = fmaf(w11, v11, val);

            unsigned long long v2;
            asm("mov.b64 %0, {%1, %1};" : "=l"(v2) : "f"(val));

            const ulonglong2* wc = wk + c * 8;   // 32 floats = 8 x ulonglong2
            #pragma unroll
            for (int j = 0; j < 8; ++j) {
                ulonglong2 ww = wc[j];
                asm("fma.rn.f32x2 %0, %1, %2, %0;"
                    : "+l"(acc[2 * j])     : "l"(v2), "l"(ww.x));
                asm("fma.rn.f32x2 %0, %1, %2, %0;"
                    : "+l"(acc[2 * j + 1]) : "l"(v2), "l"(ww.y));
            }
        }
    }

    // ---- Epilogue: out(B, Cout, Ho, Wo), this block's 32-channel slice ----
    const size_t ob = ((size_t)b * COUT + oc_base) * (HO * WO)
                    + (size_t)ho * WO + wo;
    #pragma unroll
    for (int i = 0; i < 16; ++i) {
        float lo, hi;
        asm("mov.b64 {%0, %1}, %2;" : "=f"(lo), "=f"(hi) : "l"(acc[i]));
        out[ob + (size_t)(2 * i)     * (HO * WO)] = lo;
        out[ob + (size_t)(2 * i + 1) * (HO * WO)] = hi;
    }
}

extern "C" void kernel_launch(void* const* d_in, const int* in_sizes, int n_in,
                              void* d_out, int out_size)
{
    const float* x      = (const float*)d_in[0];
    const float* offset = (const float*)d_in[1];
    const float* weight = (const float*)d_in[2];
    const float* bias   = (const float*)d_in[3];
    float* out = (float*)d_out;

    cudaFuncSetAttribute(deform_conv_kernel,
                         cudaFuncAttributeMaxDynamicSharedMemorySize, SMEM_BYTES);

    dim3 grid(NPIX / THREADS, COUT / COB);   // (512, 2)
    deform_conv_kernel<<<grid, THREADS, SMEM_BYTES>>>(
        x, offset, weight, bias, out);
}

// round 6
// speedup vs baseline: 2.4388x; 2.4388x over previous
#include <cuda_runtime.h>
#include <cstdint>

// Problem constants (DeformConvPack_39187281609181)
#define B_   4
#define C_   64
#define H_   128
#define W_   256
#define HW_  (H_ * W_)      // 32768
#define COUT 64
#define KK   9
#define HO   128
#define WO   256
#define NPIX (B_ * HO * WO) // 131072

#define TPX      128        // pixels per block (half an output row)
#define THREADS  256

// Scratch (allocation-free: __device__ globals)
__device__ float g_xt[B_ * HW_ * C_];    // x transposed to NHWC: [(b,h,w)][c]
__device__ float g_wt[KK * C_ * COUT];   // weights as [k][c][oc]

// ---------------------------------------------------------------------------
// x: (B,C,H,W) -> g_xt: (B,H,W,C)
__global__ void transpose_x(const float* __restrict__ x)
{
    __shared__ float tile[32][33];
    const int b   = blockIdx.z;
    const int c0  = blockIdx.y * 32;
    const int hw0 = blockIdx.x * 32;
    const int tx  = threadIdx.x & 31;
    const int ty  = threadIdx.x >> 5;      // 0..7

    const float* xb = x + (size_t)b * C_ * HW_;
    #pragma unroll
    for (int i = 0; i < 32; i += 8)
        tile[ty + i][tx] = xb[(size_t)(c0 + ty + i) * HW_ + hw0 + tx];
    __syncthreads();
    float* dst = g_xt + (size_t)b * HW_ * C_;
    #pragma unroll
    for (int i = 0; i < 32; i += 8)
        dst[(size_t)(hw0 + ty + i) * C_ + c0 + tx] = tile[tx][ty + i];
}

// weight: (Cout, Cin, 3, 3) -> g_wt: [k][c][oc]
__global__ void transpose_w(const float* __restrict__ w)
{
    int t = blockIdx.x * 256 + threadIdx.x;          // 0..36863
    if (t < KK * C_ * COUT) {
        int k  = t >> 12;
        int c  = (t >> 6) & 63;
        int oc = t & 63;
        g_wt[t] = w[oc * (C_ * KK) + c * KK + k];
    }
}

// ---------------------------------------------------------------------------
// Main kernel: per-k (gather 128px x 64c tile into smem) -> tiled GEMM
__global__ void __launch_bounds__(THREADS, 3)
deform_main(const float* __restrict__ offset,
            const float* __restrict__ bias,
            float* __restrict__ out)
{
    extern __shared__ char smraw[];
    float*  v_s  = (float*)smraw;                   // [c][128] rotated: 32KB
    float*  w_s  = v_s + C_ * 128;                  // [c][oc]: 16KB
    float4* mw_s = (float4*)(w_s + C_ * COUT);      // corner weights: 2KB
    int4*   mi_s = (int4*)(mw_s + TPX);             // corner bases:   2KB

    const int tid = threadIdx.x;
    const int p0  = blockIdx.x * TPX;
    const int b   = p0 >> 15;
    const int ho  = (p0 & 32767) >> 8;
    const int wo0 = p0 & 255;                       // 0 or 128

    // GEMM tiling: thread -> 4 consecutive px, 8 consecutive oc
    const int px0 = (tid & 31) * 4;
    const int oc0 = (tid >> 5) * 8;

    // acc[px][ocpair] packed f32x2, init with bias
    unsigned long long acc[4][4];
    {
        unsigned long long b2[4];
        #pragma unroll
        for (int j = 0; j < 4; ++j) {
            float2 t = __ldg((const float2*)(bias + oc0) + j);
            asm("mov.b64 %0, {%1, %2};" : "=l"(b2[j]) : "f"(t.x), "f"(t.y));
        }
        #pragma unroll
        for (int i = 0; i < 4; ++i)
            #pragma unroll
            for (int j = 0; j < 4; ++j)
                acc[i][j] = b2[j];
    }

    #pragma unroll 1
    for (int k = 0; k < KK; ++k) {
        __syncthreads();   // WAR: previous GEMM finished reading v_s/w_s/meta

        // ---- Stage 0: bilinear meta for 128 pixels (threads 0..127) ----
        if (tid < TPX) {
            const int wo = wo0 + tid;
            const size_t ob = (((size_t)b * (2 * KK) + 2 * k) * HO + ho) * WO + wo;
            const float dy = __ldg(offset + ob);
            const float dx = __ldg(offset + ob + (size_t)HO * WO);

            const int ky = k / 3, kx = k - 3 * ky;
            const float py = (float)(ho - 1 + ky) + dy;
            const float px = (float)(wo - 1 + kx) + dx;
            const float y0f = floorf(py), x0f = floorf(px);
            const float ly = py - y0f,  lx = px - x0f;
            const int y0 = (int)y0f, x0 = (int)x0f;
            const int y1 = y0 + 1,   x1 = x0 + 1;

            const float vy0 = (y0 >= 0 && y0 < H_) ? 1.0f : 0.0f;
            const float vy1 = (y1 >= 0 && y1 < H_) ? 1.0f : 0.0f;
            const float vx0 = (x0 >= 0 && x0 < W_) ? 1.0f : 0.0f;
            const float vx1 = (x1 >= 0 && x1 < W_) ? 1.0f : 0.0f;

            float4 w4;
            w4.x = (1.0f - ly) * (1.0f - lx) * vy0 * vx0;
            w4.y = (1.0f - ly) * lx          * vy0 * vx1;
            w4.z = ly          * (1.0f - lx) * vy1 * vx0;
            w4.w = ly          * lx          * vy1 * vx1;

            const int y0c = min(max(y0, 0), H_ - 1);
            const int y1c = min(max(y1, 0), H_ - 1);
            const int x0c = min(max(x0, 0), W_ - 1);
            const int x1c = min(max(x1, 0), W_ - 1);

            const int base = b * HW_;
            int4 i4;
            i4.x = (base + y0c * W_ + x0c) * C_;
            i4.y = (base + y0c * W_ + x1c) * C_;
            i4.z = (base + y1c * W_ + x0c) * C_;
            i4.w = (base + y1c * W_ + x1c) * C_;
            mw_s[tid] = w4;
            mi_s[tid] = i4;
        }

        // ---- load this k's weight slab [c][oc] (coalesced float4) ----
        {
            const float4* src = (const float4*)(g_wt + k * (C_ * COUT));
            float4* dst = (float4*)w_s;
            #pragma unroll
            for (int i = 0; i < (C_ * COUT / 4); i += THREADS)
                dst[i + tid] = src[i + tid];
        }

        __syncthreads();   // meta + weights visible

        // ---- Stage 1: cooperative gather -> v_s ----
        // task tau: px = tau>>4, c4 = (tau&15)*4. Half-warp covers one pixel's
        // 64 channels -> each LDG.128 warp-op touches 4 cache lines (2 pixels).
        #pragma unroll
        for (int it = 0; it < 8; ++it) {
            const int tau = it * THREADS + tid;
            const int px  = tau >> 4;
            const int c4  = (tau & 15) * 4;

            const float4 w4 = mw_s[px];
            const int4   i4 = mi_s[px];
            const int    f4 = c4 >> 2;

            const float4 a = __ldg((const float4*)(g_xt + i4.x) + f4);
            const float4 bq= __ldg((const float4*)(g_xt + i4.y) + f4);
            const float4 cq= __ldg((const float4*)(g_xt + i4.z) + f4);
            const float4 dq= __ldg((const float4*)(g_xt + i4.w) + f4);

            float v0 = w4.x*a.x + w4.y*bq.x + w4.z*cq.x + w4.w*dq.x;
            float v1 = w4.x*a.y + w4.y*bq.y + w4.z*cq.y + w4.w*dq.y;
            float v2 = w4.x*a.z + w4.y*bq.z + w4.z*cq.z + w4.w*dq.z;
            float v3 = w4.x*a.w + w4.y*bq.w + w4.z*cq.w + w4.w*dq.w;

            // rotation swizzle: px' = (px + c4) & 127  (same for j=0..3)
            const int pxr = (px + c4) & 127;
            v_s[(c4 + 0) * 128 + pxr] = v0;
            v_s[(c4 + 1) * 128 + pxr] = v1;
            v_s[(c4 + 2) * 128 + pxr] = v2;
            v_s[(c4 + 3) * 128 + pxr] = v3;
        }

        __syncthreads();   // v_s ready

        // ---- Stage 2: GEMM  acc[4px][8oc] += v_s[c][px] * w_s[c][oc] ----
        #pragma unroll 1
        for (int c8 = 0; c8 < 8; ++c8) {
            #pragma unroll
            for (int cc = 0; cc < 8; ++cc) {
                const int c   = c8 * 8 + cc;
                const int pxr = (px0 + (c & ~3)) & 127;
                const float4 v4 = *(const float4*)&v_s[c * 128 + pxr];
                const ulonglong2 wA = *(const ulonglong2*)&w_s[c * COUT + oc0];
                const ulonglong2 wB = *(const ulonglong2*)&w_s[c * COUT + oc0 + 4];

                unsigned long long vv0, vv1, vv2, vv3;
                asm("mov.b64 %0, {%1, %1};" : "=l"(vv0) : "f"(v4.x));
                asm("mov.b64 %0, {%1, %1};" : "=l"(vv1) : "f"(v4.y));
                asm("mov.b64 %0, {%1, %1};" : "=l"(vv2) : "f"(v4.z));
                asm("mov.b64 %0, {%1, %1};" : "=l"(vv3) : "f"(v4.w));

                #define FMA2(A, V, W) \
                    asm("fma.rn.f32x2 %0, %1, %2, %0;" : "+l"(A) : "l"(V), "l"(W))
                FMA2(acc[0][0], vv0, wA.x); FMA2(acc[0][1], vv0, wA.y);
                FMA2(acc[0][2], vv0, wB.x); FMA2(acc[0][3], vv0, wB.y);
                FMA2(acc[1][0], vv1, wA.x); FMA2(acc[1][1], vv1, wA.y);
                FMA2(acc[1][2], vv1, wB.x); FMA2(acc[1][3], vv1, wB.y);
                FMA2(acc[2][0], vv2, wA.x); FMA2(acc[2][1], vv2, wA.y);
                FMA2(acc[2][2], vv2, wB.x); FMA2(acc[2][3], vv2, wB.y);
                FMA2(acc[3][0], vv3, wA.x); FMA2(acc[3][1], vv3, wA.y);
                FMA2(acc[3][2], vv3, wB.x); FMA2(acc[3][3], vv3, wB.y);
                #undef FMA2
            }
        }
    }

    // ---- Epilogue: out(B, Cout, Ho, Wo) ----
    const size_t hw_out = (size_t)ho * WO + wo0 + px0;
    #pragma unroll
    for (int j = 0; j < 4; ++j) {
        float lo[4], hi[4];
        #pragma unroll
        for (int i = 0; i < 4; ++i)
            asm("mov.b64 {%0, %1}, %2;" : "=f"(lo[i]), "=f"(hi[i]) : "l"(acc[i][j]));
        float4 r0 = make_float4(lo[0], lo[1], lo[2], lo[3]);
        float4 r1 = make_float4(hi[0], hi[1], hi[2], hi[3]);
        const int oc = oc0 + 2 * j;
        *(float4*)(out + (size_t)(b * COUT + oc    ) * HW_ + hw_out) = r0;
        *(float4*)(out + (size_t)(b * COUT + oc + 1) * HW_ + hw_out) = r1;
    }
}

// ---------------------------------------------------------------------------
extern "C" void kernel_launch(void* const* d_in, const int* in_sizes, int n_in,
                              void* d_out, int out_size)
{
    const float* x      = (const float*)d_in[0];
    const float* offset = (const float*)d_in[1];
    const float* weight = (const float*)d_in[2];
    const float* bias   = (const float*)d_in[3];
    float* out = (float*)d_out;

    const int smem = (C_ * 128 + C_ * COUT) * 4 + TPX * 16 + TPX * 16; // 53248
    cudaFuncSetAttribute(deform_main,
                         cudaFuncAttributeMaxDynamicSharedMemorySize, smem);

    transpose_x<<<dim3(HW_ / 32, C_ / 32, B_), 256>>>(x);
    transpose_w<<<(KK * C_ * COUT + 255) / 256, 256>>>(weight);
    deform_main<<<NPIX / TPX, THREADS, smem>>>(offset, bias, out);
}

// round 10
// speedup vs baseline: 2.8410x; 1.1649x over previous
#include <cuda_runtime.h>
#include <cuda_bf16.h>
#include <mma.h>
#include <cstdint>

using namespace nvcuda;

// Problem constants (DeformConvPack_39187281609181)
#define B_   4
#define C_   64
#define H_   128
#define W_   256
#define HW_  (H_ * W_)      // 32768
#define COUT 64
#define KK   9
#define HO   128
#define WO   256
#define NPIX (B_ * HO * WO) // 131072

#define TPX     128
#define THREADS 256

// smem element layout (bf16 elements unless noted)
#define LDA 72                            // padded leading dim for A (144B rows)
#define LDB 72                            // padded leading dim for W
#define A_ELEMS (TPX * LDA)               // 9216 bf16 = 18432 B
#define W_ELEMS (C_ * LDB)                // 4608 bf16 = 9216 B
// byte offsets
#define SM_AHI  0
#define SM_ALO  (SM_AHI + A_ELEMS * 2)    // 18432
#define SM_WHI  (SM_ALO + A_ELEMS * 2)    // 36864
#define SM_WLO  (SM_WHI + W_ELEMS * 2)    // 46080
#define SM_MW   (SM_WLO + W_ELEMS * 2)    // 55296 (float4[128] = 2048B)
#define SM_MI   (SM_MW + 2048)            // 57344 (int4[128]  = 2048B)
#define SM_TOTAL (SM_MI + 2048)           // 59392 B
#define LDE 68                            // epilogue fp32 ldm (128*68*4=34816B <= 36864)

// Scratch (allocation-free)
__device__ float g_xt[(size_t)B_ * HW_ * C_];       // x as NHWC
__device__ __nv_bfloat16 g_wh[KK * C_ * COUT];      // weight hi, [k][c][oc]
__device__ __nv_bfloat16 g_wl[KK * C_ * COUT];      // weight lo

// ---------------------------------------------------------------------------
// x: (B,C,H,W) -> g_xt: (B,H,W,C)
__global__ void transpose_x(const float* __restrict__ x)
{
    __shared__ float tile[32][33];
    const int b   = blockIdx.z;
    const int c0  = blockIdx.y * 32;
    const int hw0 = blockIdx.x * 32;
    const int tx  = threadIdx.x & 31;
    const int ty  = threadIdx.x >> 5;

    const float* xb = x + (size_t)b * C_ * HW_;
    #pragma unroll
    for (int i = 0; i < 32; i += 8)
        tile[ty + i][tx] = xb[(size_t)(c0 + ty + i) * HW_ + hw0 + tx];
    __syncthreads();
    float* dst = g_xt + (size_t)b * HW_ * C_;
    #pragma unroll
    for (int i = 0; i < 32; i += 8)
        dst[(size_t)(hw0 + ty + i) * C_ + c0 + tx] = tile[tx][ty + i];
}

// weight (Cout,Cin,3,3) -> split bf16 hi/lo, layout [k][c][oc]
__global__ void convert_w(const float* __restrict__ w)
{
    int t = blockIdx.x * 256 + threadIdx.x;      // 0..36863
    if (t < KK * C_ * COUT) {
        int k  = t >> 12;
        int c  = (t >> 6) & 63;
        int oc = t & 63;
        float v = w[oc * (C_ * KK) + c * KK + k];
        __nv_bfloat16 h = __float2bfloat16(v);
        float r = v - __bfloat162float(h);
        g_wh[t] = h;
        g_wl[t] = __float2bfloat16(r);
    }
}

// ---------------------------------------------------------------------------
__global__ void __launch_bounds__(THREADS, 2)
deform_main(const float* __restrict__ offset,
            const float* __restrict__ bias,
            float* __restrict__ out)
{
    extern __shared__ char sm[];
    __nv_bfloat16* a_hi = (__nv_bfloat16*)(sm + SM_AHI);
    __nv_bfloat16* a_lo = (__nv_bfloat16*)(sm + SM_ALO);
    __nv_bfloat16* w_hi = (__nv_bfloat16*)(sm + SM_WHI);
    __nv_bfloat16* w_lo = (__nv_bfloat16*)(sm + SM_WLO);
    float4*        mw_s = (float4*)(sm + SM_MW);
    int4*          mi_s = (int4*)(sm + SM_MI);

    const int tid = threadIdx.x;
    const int wid = tid >> 5;

    const int p0  = blockIdx.x * TPX;
    const int b   = p0 >> 15;
    const int ho  = (p0 & 32767) >> 8;
    const int wo0 = p0 & 255;

    // Accumulators: warp wid owns px rows [16*wid, 16*wid+16), all 64 oc
    wmma::fragment<wmma::accumulator, 16, 16, 16, float> acc[4];
    #pragma unroll
    for (int n = 0; n < 4; ++n) wmma::fill_fragment(acc[n], 0.0f);

    #pragma unroll 1
    for (int k = 0; k < KK; ++k) {
        __syncthreads();   // prev GEMM done reading A/W; epilogue not yet

        // ---- Phase 1: bilinear meta (tid<128) + W slab staging (all) ----
        if (tid < TPX) {
            const int wo = wo0 + tid;
            const size_t ob = (((size_t)b * (2 * KK) + 2 * k) * HO + ho) * WO + wo;
            const float dy = __ldg(offset + ob);
            const float dx = __ldg(offset + ob + (size_t)HO * WO);

            const int ky = k / 3, kx = k - 3 * ky;
            const float py = (float)(ho - 1 + ky) + dy;
            const float px = (float)(wo - 1 + kx) + dx;
            const float y0f = floorf(py), x0f = floorf(px);
            const float ly = py - y0f,  lx = px - x0f;
            const int y0 = (int)y0f, x0 = (int)x0f;
            const int y1 = y0 + 1,   x1 = x0 + 1;

            const float vy0 = (y0 >= 0 && y0 < H_) ? 1.0f : 0.0f;
            const float vy1 = (y1 >= 0 && y1 < H_) ? 1.0f : 0.0f;
            const float vx0 = (x0 >= 0 && x0 < W_) ? 1.0f : 0.0f;
            const float vx1 = (x1 >= 0 && x1 < W_) ? 1.0f : 0.0f;

            float4 w4;
            w4.x = (1.0f - ly) * (1.0f - lx) * vy0 * vx0;
            w4.y = (1.0f - ly) * lx          * vy0 * vx1;
            w4.z = ly          * (1.0f - lx) * vy1 * vx0;
            w4.w = ly          * lx          * vy1 * vx1;

            const int y0c = min(max(y0, 0), H_ - 1);
            const int y1c = min(max(y1, 0), H_ - 1);
            const int x0c = min(max(x0, 0), W_ - 1);
            const int x1c = min(max(x1, 0), W_ - 1);

            const int base = b * HW_;
            int4 i4;
            i4.x = (base + y0c * W_ + x0c) * C_;
            i4.y = (base + y0c * W_ + x1c) * C_;
            i4.z = (base + y1c * W_ + x0c) * C_;
            i4.w = (base + y1c * W_ + x1c) * C_;
            mw_s[tid] = w4;
            mi_s[tid] = i4;
        }
        {
            // W slab k: 4096 bf16 hi + 4096 lo; as 2048 words each.
            // word i -> c = i>>5, oc2 = i&31 ; dst bf16 idx c*LDB + oc2*2
            const uint32_t* sh = (const uint32_t*)(g_wh + k * (C_ * COUT));
            const uint32_t* sl = (const uint32_t*)(g_wl + k * (C_ * COUT));
            #pragma unroll
            for (int j = 0; j < 8; ++j) {
                const int i  = j * THREADS + tid;
                const int c  = i >> 5;
                const int o2 = i & 31;
                *(uint32_t*)(w_hi + c * LDB + o2 * 2) = __ldg(sh + i);
                *(uint32_t*)(w_lo + c * LDB + o2 * 2) = __ldg(sl + i);
            }
        }
        __syncthreads();

        // ---- Phase 2: gather + bilinear + bf16 split -> A tiles ----
        #pragma unroll
        for (int it = 0; it < 8; ++it) {
            const int tau = it * THREADS + tid;
            const int px  = tau >> 4;
            const int c4  = (tau & 15) * 4;

            const float4 w4 = mw_s[px];
            const int4   i4 = mi_s[px];
            const int    f4 = c4 >> 2;

            const float4 a  = __ldg((const float4*)(g_xt + i4.x) + f4);
            const float4 bq = __ldg((const float4*)(g_xt + i4.y) + f4);
            const float4 cq = __ldg((const float4*)(g_xt + i4.z) + f4);
            const float4 dq = __ldg((const float4*)(g_xt + i4.w) + f4);

            float v0 = w4.x*a.x + w4.y*bq.x + w4.z*cq.x + w4.w*dq.x;
            float v1 = w4.x*a.y + w4.y*bq.y + w4.z*cq.y + w4.w*dq.y;
            float v2 = w4.x*a.z + w4.y*bq.z + w4.z*cq.z + w4.w*dq.z;
            float v3 = w4.x*a.w + w4.y*bq.w + w4.z*cq.w + w4.w*dq.w;

            uint32_t h01, h23, l01, l23;
            asm("cvt.rn.satfinite.bf16x2.f32 %0, %1, %2;" : "=r"(h01) : "f"(v1), "f"(v0));
            asm("cvt.rn.satfinite.bf16x2.f32 %0, %1, %2;" : "=r"(h23) : "f"(v3), "f"(v2));
            const float r0 = v0 - __uint_as_float(h01 << 16);
            const float r1 = v1 - __uint_as_float(h01 & 0xFFFF0000u);
            const float r2 = v2 - __uint_as_float(h23 << 16);
            const float r3 = v3 - __uint_as_float(h23 & 0xFFFF0000u);
            asm("cvt.rn.satfinite.bf16x2.f32 %0, %1, %2;" : "=r"(l01) : "f"(r1), "f"(r0));
            asm("cvt.rn.satfinite.bf16x2.f32 %0, %1, %2;" : "=r"(l23) : "f"(r3), "f"(r2));

            *(uint2*)(a_hi + px * LDA + c4) = make_uint2(h01, h23);
            *(uint2*)(a_lo + px * LDA + c4) = make_uint2(l01, l23);
        }
        __syncthreads();

        // ---- Phase 3: wmma GEMM, acc[px 16-row band][4 n-tiles] ----
        {
            const __nv_bfloat16* arow_h = a_hi + wid * 16 * LDA;
            const __nv_bfloat16* arow_l = a_lo + wid * 16 * LDA;
            #pragma unroll
            for (int kt = 0; kt < 4; ++kt) {
                wmma::fragment<wmma::matrix_a, 16, 16, 16, __nv_bfloat16,
                               wmma::row_major> fa_h, fa_l;
                wmma::load_matrix_sync(fa_h, arow_h + kt * 16, LDA);
                wmma::load_matrix_sync(fa_l, arow_l + kt * 16, LDA);
                #pragma unroll
                for (int nt = 0; nt < 4; ++nt) {
                    wmma::fragment<wmma::matrix_b, 16, 16, 16, __nv_bfloat16,
                                   wmma::row_major> fb_h, fb_l;
                    wmma::load_matrix_sync(fb_h, w_hi + kt * 16 * LDB + nt * 16, LDB);
                    wmma::load_matrix_sync(fb_l, w_lo + kt * 16 * LDB + nt * 16, LDB);
                    wmma::mma_sync(acc[nt], fa_h, fb_h, acc[nt]);
                    wmma::mma_sync(acc[nt], fa_h, fb_l, acc[nt]);
                    wmma::mma_sync(acc[nt], fa_l, fb_h, acc[nt]);
                }
            }
        }
    }

    // ---- Epilogue: acc -> fp32 smem [128][LDE] -> transposed coalesced STG ----
    __syncthreads();                       // all GEMM reads of A done
    {
        float* smf = (float*)sm;           // reuses A region (34816 <= 36864)
        #pragma unroll
        for (int nt = 0; nt < 4; ++nt)
            wmma::store_matrix_sync(smf + wid * 16 * LDE + nt * 16, acc[nt],
                                    LDE, wmma::mem_row_major);
    }
    __syncthreads();
    {
        const float* smf = (const float*)sm;
        const int oc_g = tid >> 7;                    // 0/1
        const int pxe  = tid & 127;
        const size_t hw_out = (size_t)ho * WO + wo0 + pxe;
        #pragma unroll
        for (int o2 = 0; o2 < 32; ++o2) {
            const int oc = oc_g * 32 + o2;
            out[(size_t)(b * COUT + oc) * HW_ + hw_out] =
                smf[pxe * LDE + oc] + __ldg(bias + oc);
        }
    }
}

// ---------------------------------------------------------------------------
extern "C" void kernel_launch(void* const* d_in, const int* in_sizes, int n_in,
                              void* d_out, int out_size)
{
    const float* x      = (const float*)d_in[0];
    const float* offset = (const float*)d_in[1];
    const float* weight = (const float*)d_in[2];
    const float* bias   = (const float*)d_in[3];
    float* out = (float*)d_out;

    cudaFuncSetAttribute(deform_main,
                         cudaFuncAttributeMaxDynamicSharedMemorySize, SM_TOTAL);

    transpose_x<<<dim3(HW_ / 32, C_ / 32, B_), 256>>>(x);
    convert_w<<<(KK * C_ * COUT + 255) / 256, 256>>>(weight);
    deform_main<<<NPIX / TPX, THREADS, SM_TOTAL>>>(offset, bias, out);
}

// round 11
// speedup vs baseline: 3.0064x; 1.0582x over previous
#include <cuda_runtime.h>
#include <cuda_bf16.h>
#include <mma.h>
#include <cstdint>

using namespace nvcuda;

// Problem constants (DeformConvPack_39187281609181)
#define B_   4
#define C_   64
#define H_   128
#define W_   256
#define HW_  (H_ * W_)      // 32768
#define COUT 64
#define KK   9
#define HO   128
#define WO   256
#define NPIX (B_ * HO * WO) // 131072

#define TPX     128
#define THREADS 256

// smem layout (bytes)
#define LDA 72                             // A leading dim (144B rows, ldmatrix conflict-free)
#define LDB 72
#define A_BYTES (TPX * LDA * 2)            // 18432 per (hi|lo)
#define W_HALF  (C_ * LDB * 2)             // 9216  per (hi|lo)
#define W_BUF   (2 * W_HALF)               // 18432 per buffer (hi+lo)
#define SM_AHI  0
#define SM_ALO  (SM_AHI + A_BYTES)         // 18432
#define SM_W    (SM_ALO + A_BYTES)         // 36864 ; two buffers of W_BUF
#define SM_TOTAL (SM_W + 2 * W_BUF)        // 73728 -> 3 CTAs/SM
#define LDE 68                             // epilogue fp32 ldm (128*68*4=34816 <= 36864)

// Scratch (allocation-free)
__device__ float g_xt[(size_t)B_ * HW_ * C_];       // x as NHWC
__device__ __nv_bfloat16 g_wh[KK * C_ * COUT];      // weight hi, [k][c][oc]
__device__ __nv_bfloat16 g_wl[KK * C_ * COUT];      // weight lo

__device__ __forceinline__ uint32_t smem_u32(const void* p) {
    uint32_t a;
    asm("{ .reg .u64 t; cvta.to.shared.u64 t, %1; cvt.u32.u64 %0, t; }"
        : "=r"(a) : "l"(p));
    return a;
}
__device__ __forceinline__ void cp_async16(uint32_t dst, const void* src) {
    asm volatile("cp.async.ca.shared.global [%0], [%1], 16;"
                 :: "r"(dst), "l"(src) : "memory");
}

// ---------------------------------------------------------------------------
// x: (B,C,H,W) -> g_xt: (B,H,W,C)
__global__ void transpose_x(const float* __restrict__ x)
{
    __shared__ float tile[32][33];
    const int b   = blockIdx.z;
    const int c0  = blockIdx.y * 32;
    const int hw0 = blockIdx.x * 32;
    const int tx  = threadIdx.x & 31;
    const int ty  = threadIdx.x >> 5;

    const float* xb = x + (size_t)b * C_ * HW_;
    #pragma unroll
    for (int i = 0; i < 32; i += 8)
        tile[ty + i][tx] = xb[(size_t)(c0 + ty + i) * HW_ + hw0 + tx];
    __syncthreads();
    float* dst = g_xt + (size_t)b * HW_ * C_;
    #pragma unroll
    for (int i = 0; i < 32; i += 8)
        dst[(size_t)(hw0 + ty + i) * C_ + c0 + tx] = tile[tx][ty + i];
}

// weight (Cout,Cin,3,3) -> split bf16 hi/lo, layout [k][c][oc]
__global__ void convert_w(const float* __restrict__ w)
{
    int t = blockIdx.x * 256 + threadIdx.x;      // 0..36863
    if (t < KK * C_ * COUT) {
        int k  = t >> 12;
        int c  = (t >> 6) & 63;
        int oc = t & 63;
        float v = w[oc * (C_ * KK) + c * KK + k];
        __nv_bfloat16 h = __float2bfloat16(v);
        float r = v - __bfloat162float(h);
        g_wh[t] = h;
        g_wl[t] = __float2bfloat16(r);
    }
}

// ---------------------------------------------------------------------------
__global__ void __launch_bounds__(THREADS, 3)
deform_main(const float* __restrict__ offset,
            const float* __restrict__ bias,
            float* __restrict__ out)
{
    extern __shared__ char sm[];
    __nv_bfloat16* a_hi = (__nv_bfloat16*)(sm + SM_AHI);
    __nv_bfloat16* a_lo = (__nv_bfloat16*)(sm + SM_ALO);
    const uint32_t smb  = smem_u32(sm);

    const int tid = threadIdx.x;
    const int wid = tid >> 5;
    const int lid = tid & 31;

    const int p0  = blockIdx.x * TPX;
    const int b   = p0 >> 15;
    const int ho  = (p0 & 32767) >> 8;
    const int wo0 = p0 & 255;

    // Accumulators: warp wid owns px rows [16*wid, 16*wid+16), all 64 oc
    wmma::fragment<wmma::accumulator, 16, 16, 16, float> acc[4];
    #pragma unroll
    for (int n = 0; n < 4; ++n) wmma::fill_fragment(acc[n], 0.0f);

    #pragma unroll 1
    for (int k = 0; k < KK; ++k) {
        // ---- stage W(k) -> buf k&1 via cp.async (each warp: 8 c-rows) ----
        {
            const uint32_t wb = smb + SM_W + (k & 1) * W_BUF;
            const int c = wid * 8 + (lid >> 2);
            const __nv_bfloat16* sh = g_wh + k * (C_ * COUT) + c * COUT;
            const __nv_bfloat16* sl = g_wl + k * (C_ * COUT) + c * COUT;
            #pragma unroll
            for (int j = 0; j < 2; ++j) {
                const int seg = (lid & 3) + 4 * j;          // 0..7, 16B each
                cp_async16(wb + c * 144 + seg * 16,          sh + seg * 8);
                cp_async16(wb + W_HALF + c * 144 + seg * 16, sl + seg * 8);
            }
            asm volatile("cp.async.commit_group;" ::: "memory");
        }

        // ---- warp-local bilinear meta for pixel 16*wid + (lid&15) ----
        float4 w4m; int4 i4m;
        {
            const int pxl = lid & 15;
            const int wo  = wo0 + wid * 16 + pxl;
            const size_t ob = (((size_t)b * (2 * KK) + 2 * k) * HO + ho) * WO + wo;
            const float dy = __ldg(offset + ob);
            const float dx = __ldg(offset + ob + (size_t)HO * WO);

            const int ky = k / 3, kx = k - 3 * ky;
            const float py = (float)(ho - 1 + ky) + dy;
            const float px = (float)(wo - 1 + kx) + dx;
            const float y0f = floorf(py), x0f = floorf(px);
            const float ly = py - y0f,  lx = px - x0f;
            const int y0 = (int)y0f, x0 = (int)x0f;
            const int y1 = y0 + 1,   x1 = x0 + 1;

            const float vy0 = (y0 >= 0 && y0 < H_) ? 1.0f : 0.0f;
            const float vy1 = (y1 >= 0 && y1 < H_) ? 1.0f : 0.0f;
            const float vx0 = (x0 >= 0 && x0 < W_) ? 1.0f : 0.0f;
            const float vx1 = (x1 >= 0 && x1 < W_) ? 1.0f : 0.0f;

            w4m.x = (1.0f - ly) * (1.0f - lx) * vy0 * vx0;
            w4m.y = (1.0f - ly) * lx          * vy0 * vx1;
            w4m.z = ly          * (1.0f - lx) * vy1 * vx0;
            w4m.w = ly          * lx          * vy1 * vx1;

            const int y0c = min(max(y0, 0), H_ - 1);
            const int y1c = min(max(y1, 0), H_ - 1);
            const int x0c = min(max(x0, 0), W_ - 1);
            const int x1c = min(max(x1, 0), W_ - 1);

            const int base = b * HW_;
            i4m.x = (base + y0c * W_ + x0c) * C_;
            i4m.y = (base + y0c * W_ + x1c) * C_;
            i4m.z = (base + y1c * W_ + x0c) * C_;
            i4m.w = (base + y1c * W_ + x1c) * C_;
        }

        // ---- gather: warp covers its 16 px x 64 c; 8 iterations ----
        #pragma unroll
        for (int it = 0; it < 8; ++it) {
            const int src = it * 2 + (lid >> 4);            // meta source lane
            const float wx = __shfl_sync(0xffffffffu, w4m.x, src);
            const float wy = __shfl_sync(0xffffffffu, w4m.y, src);
            const float wz = __shfl_sync(0xffffffffu, w4m.z, src);
            const float ww = __shfl_sync(0xffffffffu, w4m.w, src);
            const int   ia = __shfl_sync(0xffffffffu, i4m.x, src);
            const int   ib = __shfl_sync(0xffffffffu, i4m.y, src);
            const int   ic = __shfl_sync(0xffffffffu, i4m.z, src);
            const int   id = __shfl_sync(0xffffffffu, i4m.w, src);

            const int c4 = (lid & 15) * 4;
            const int f4 = lid & 15;

            const float4 a  = __ldg((const float4*)(g_xt + ia) + f4);
            const float4 bq = __ldg((const float4*)(g_xt + ib) + f4);
            const float4 cq = __ldg((const float4*)(g_xt + ic) + f4);
            const float4 dq = __ldg((const float4*)(g_xt + id) + f4);

            float v0 = wx*a.x + wy*bq.x + wz*cq.x + ww*dq.x;
            float v1 = wx*a.y + wy*bq.y + wz*cq.y + ww*dq.y;
            float v2 = wx*a.z + wy*bq.z + wz*cq.z + ww*dq.z;
            float v3 = wx*a.w + wy*bq.w + wz*cq.w + ww*dq.w;

            uint32_t h01, h23, l01, l23;
            asm("cvt.rn.satfinite.bf16x2.f32 %0, %1, %2;" : "=r"(h01) : "f"(v1), "f"(v0));
            asm("cvt.rn.satfinite.bf16x2.f32 %0, %1, %2;" : "=r"(h23) : "f"(v3), "f"(v2));
            const float r0 = v0 - __uint_as_float(h01 << 16);
            const float r1 = v1 - __uint_as_float(h01 & 0xFFFF0000u);
            const float r2 = v2 - __uint_as_float(h23 << 16);
            const float r3 = v3 - __uint_as_float(h23 & 0xFFFF0000u);
            asm("cvt.rn.satfinite.bf16x2.f32 %0, %1, %2;" : "=r"(l01) : "f"(r1), "f"(r0));
            asm("cvt.rn.satfinite.bf16x2.f32 %0, %1, %2;" : "=r"(l23) : "f"(r3), "f"(r2));

            const int row = wid * 16 + it * 2 + (lid >> 4); // warp-private A row
            *(uint2*)(a_hi + row * LDA + c4) = make_uint2(h01, h23);
            *(uint2*)(a_lo + row * LDA + c4) = make_uint2(l01, l23);
        }

        asm volatile("cp.async.wait_group 0;" ::: "memory");
        __syncthreads();   // the ONE barrier: W(k) visible; orders W-buf WAR

        // ---- GEMM: acc[16-row band][4 n-tiles] over this k's 64 channels ----
        {
            const __nv_bfloat16* w_hi =
                (const __nv_bfloat16*)(sm + SM_W + (k & 1) * W_BUF);
            const __nv_bfloat16* w_lo = w_hi + C_ * LDB;
            const __nv_bfloat16* arow_h = a_hi + wid * 16 * LDA;
            const __nv_bfloat16* arow_l = a_lo + wid * 16 * LDA;
            #pragma unroll
            for (int kt = 0; kt < 4; ++kt) {
                wmma::fragment<wmma::matrix_a, 16, 16, 16, __nv_bfloat16,
                               wmma::row_major> fa_h, fa_l;
                wmma::load_matrix_sync(fa_h, arow_h + kt * 16, LDA);
                wmma::load_matrix_sync(fa_l, arow_l + kt * 16, LDA);
                #pragma unroll
                for (int nt = 0; nt < 4; ++nt) {
                    wmma::fragment<wmma::matrix_b, 16, 16, 16, __nv_bfloat16,
                                   wmma::row_major> fb_h, fb_l;
                    wmma::load_matrix_sync(fb_h, w_hi + kt * 16 * LDB + nt * 16, LDB);
                    wmma::load_matrix_sync(fb_l, w_lo + kt * 16 * LDB + nt * 16, LDB);
                    wmma::mma_sync(acc[nt], fa_h, fb_h, acc[nt]);
                    wmma::mma_sync(acc[nt], fa_h, fb_l, acc[nt]);
                    wmma::mma_sync(acc[nt], fa_l, fb_h, acc[nt]);
                }
            }
        }
    }

    // ---- Epilogue: acc -> fp32 smem [128][LDE] -> transposed coalesced STG ----
    __syncthreads();                       // all warps done with A/W smem
    {
        float* smf = (float*)sm;           // reuse (34816 <= 36864)
        #pragma unroll
        for (int nt = 0; nt < 4; ++nt)
            wmma::store_matrix_sync(smf + wid * 16 * LDE + nt * 16, acc[nt],
                                    LDE, wmma::mem_row_major);
    }
    __syncthreads();
    {
        const float* smf = (const float*)sm;
        const int oc_g = tid >> 7;                    // 0/1
        const int pxe  = tid & 127;
        const size_t hw_out = (size_t)ho * WO + wo0 + pxe;
        #pragma unroll
        for (int o2 = 0; o2 < 32; ++o2) {
            const int oc = oc_g * 32 + o2;
            out[(size_t)(b * COUT + oc) * HW_ + hw_out] =
                smf[pxe * LDE + oc] + __ldg(bias + oc);
        }
    }
}

// ---------------------------------------------------------------------------
extern "C" void kernel_launch(void* const* d_in, const int* in_sizes, int n_in,
                              void* d_out, int out_size)
{
    const float* x      = (const float*)d_in[0];
    const float* offset = (const float*)d_in[1];
    const float* weight = (const float*)d_in[2];
    const float* bias   = (const float*)d_in[3];
    float* out = (float*)d_out;

    cudaFuncSetAttribute(deform_main,
                         cudaFuncAttributeMaxDynamicSharedMemorySize, SM_TOTAL);

    transpose_x<<<dim3(HW_ / 32, C_ / 32, B_), 256>>>(x);
    convert_w<<<(KK * C_ * COUT + 255) / 256, 256>>>(weight);
    deform_main<<<NPIX / TPX, THREADS, SM_TOTAL>>>(offset, bias, out);
}

// round 12
// speedup vs baseline: 4.8166x; 1.6021x over previous
#include <cuda_runtime.h>
#include <cuda_fp16.h>
#include <mma.h>
#include <cstdint>

using namespace nvcuda;

// Problem constants (DeformConvPack_39187281609181)
#define B_   4
#define C_   64
#define H_   128
#define W_   256
#define HW_  (H_ * W_)      // 32768
#define COUT 64
#define KK   9
#define HO   128
#define WO   256
#define NPIX (B_ * HO * WO) // 131072

#define TPX     128
#define THREADS 256

// smem layout (bytes)
#define LDA 72                             // A leading dim (144B rows, ldmatrix conflict-free)
#define LDB 72
#define A_BYTES (TPX * LDA * 2)            // 18432
#define W_BUF   (C_ * LDB * 2)             // 9216 per buffer
#define SM_A    0
#define SM_W    (SM_A + A_BYTES)           // 18432 ; two buffers
#define SM_TOTAL (SM_W + 2 * W_BUF)        // 36864
#define LDE 68                             // epilogue fp32 ldm (128*68*4=34816 <= 36864)

// Scratch (allocation-free)
__device__ float  g_xt[(size_t)B_ * HW_ * C_];   // x as NHWC
__device__ __half g_wf[KK * C_ * COUT];          // weight fp16, [k][c][oc]

__device__ __forceinline__ uint32_t smem_u32(const void* p) {
    uint32_t a;
    asm("{ .reg .u64 t; cvta.to.shared.u64 t, %1; cvt.u32.u64 %0, t; }"
        : "=r"(a) : "l"(p));
    return a;
}
__device__ __forceinline__ void cp_async16(uint32_t dst, const void* src) {
    asm volatile("cp.async.ca.shared.global [%0], [%1], 16;"
                 :: "r"(dst), "l"(src) : "memory");
}

// ---------------------------------------------------------------------------
// Merged prep: blocks [0,8192) transpose x NCHW->NHWC; blocks [8192,8336) cvt W
__global__ void prep(const float* __restrict__ x, const float* __restrict__ w)
{
    if (blockIdx.x < 8192) {
        __shared__ float tile[32][33];
        const int bi  = blockIdx.x;
        const int b   = bi >> 11;
        const int c0  = ((bi >> 10) & 1) * 32;
        const int hw0 = (bi & 1023) * 32;
        const int tx  = threadIdx.x & 31;
        const int ty  = threadIdx.x >> 5;

        const float* xb = x + (size_t)b * C_ * HW_;
        #pragma unroll
        for (int i = 0; i < 32; i += 8)
            tile[ty + i][tx] = xb[(size_t)(c0 + ty + i) * HW_ + hw0 + tx];
        __syncthreads();
        float* dst = g_xt + (size_t)b * HW_ * C_;
        #pragma unroll
        for (int i = 0; i < 32; i += 8)
            dst[(size_t)(hw0 + ty + i) * C_ + c0 + tx] = tile[tx][ty + i];
    } else {
        // weight (Cout,Cin,3,3) -> fp16 [k][c][oc]
        const int t = (blockIdx.x - 8192) * 256 + threadIdx.x;   // 0..36863
        if (t < KK * C_ * COUT) {
            const int k  = t >> 12;
            const int c  = (t >> 6) & 63;
            const int oc = t & 63;
            g_wf[t] = __float2half(w[oc * (C_ * KK) + c * KK + k]);
        }
    }
}

// ---------------------------------------------------------------------------
__global__ void __launch_bounds__(THREADS, 3)
deform_main(const float* __restrict__ offset,
            const float* __restrict__ bias,
            float* __restrict__ out)
{
    extern __shared__ char sm[];
    __half*        a_s = (__half*)(sm + SM_A);
    const uint32_t smb = smem_u32(sm);

    const int tid = threadIdx.x;
    const int wid = tid >> 5;
    const int lid = tid & 31;

    const int p0  = blockIdx.x * TPX;
    const int b   = p0 >> 15;
    const int ho  = (p0 & 32767) >> 8;
    const int wo0 = p0 & 255;

    // Accumulators: warp wid owns px rows [16*wid, 16*wid+16), all 64 oc
    wmma::fragment<wmma::accumulator, 16, 16, 16, float> acc[4];
    #pragma unroll
    for (int n = 0; n < 4; ++n) wmma::fill_fragment(acc[n], 0.0f);

    #pragma unroll 1
    for (int k = 0; k < KK; ++k) {
        // ---- stage W(k) -> buf k&1 via cp.async (warp: 8 c-rows of 128B) ----
        {
            const uint32_t wb = smb + SM_W + (k & 1) * W_BUF;
            const int c   = wid * 8 + (lid >> 2);
            const __half* src = g_wf + k * (C_ * COUT) + c * COUT;
            #pragma unroll
            for (int j = 0; j < 2; ++j) {
                const int seg = (lid & 3) * 2 + j;          // 0..7, 16B each
                cp_async16(wb + c * 144 + seg * 16, src + seg * 8);
            }
            asm volatile("cp.async.commit_group;" ::: "memory");
        }

        // ---- warp-local bilinear meta for pixel 16*wid + (lid&15) ----
        float4 w4m; int4 i4m;
        {
            const int pxl = lid & 15;
            const int wo  = wo0 + wid * 16 + pxl;
            const size_t ob = (((size_t)b * (2 * KK) + 2 * k) * HO + ho) * WO + wo;
            const float dy = __ldg(offset + ob);
            const float dx = __ldg(offset + ob + (size_t)HO * WO);

            const int ky = k / 3, kx = k - 3 * ky;
            const float py = (float)(ho - 1 + ky) + dy;
            const float px = (float)(wo - 1 + kx) + dx;
            const float y0f = floorf(py), x0f = floorf(px);
            const float ly = py - y0f,  lx = px - x0f;
            const int y0 = (int)y0f, x0 = (int)x0f;
            const int y1 = y0 + 1,   x1 = x0 + 1;

            const float vy0 = (y0 >= 0 && y0 < H_) ? 1.0f : 0.0f;
            const float vy1 = (y1 >= 0 && y1 < H_) ? 1.0f : 0.0f;
            const float vx0 = (x0 >= 0 && x0 < W_) ? 1.0f : 0.0f;
            const float vx1 = (x1 >= 0 && x1 < W_) ? 1.0f : 0.0f;

            w4m.x = (1.0f - ly) * (1.0f - lx) * vy0 * vx0;
            w4m.y = (1.0f - ly) * lx          * vy0 * vx1;
            w4m.z = ly          * (1.0f - lx) * vy1 * vx0;
            w4m.w = ly          * lx          * vy1 * vx1;

            const int y0c = min(max(y0, 0), H_ - 1);
            const int y1c = min(max(y1, 0), H_ - 1);
            const int x0c = min(max(x0, 0), W_ - 1);
            const int x1c = min(max(x1, 0), W_ - 1);

            const int base = b * HW_;
            i4m.x = (base + y0c * W_ + x0c) * C_;
            i4m.y = (base + y0c * W_ + x1c) * C_;
            i4m.z = (base + y1c * W_ + x0c) * C_;
            i4m.w = (base + y1c * W_ + x1c) * C_;
        }

        // ---- gather: warp covers its 16 px x 64 c; 8 iterations ----
        #pragma unroll
        for (int it = 0; it < 8; ++it) {
            const int src = it * 2 + (lid >> 4);            // meta source lane
            const float wx = __shfl_sync(0xffffffffu, w4m.x, src);
            const float wy = __shfl_sync(0xffffffffu, w4m.y, src);
            const float wz = __shfl_sync(0xffffffffu, w4m.z, src);
            const float ww = __shfl_sync(0xffffffffu, w4m.w, src);
            const int   ia = __shfl_sync(0xffffffffu, i4m.x, src);
            const int   ib = __shfl_sync(0xffffffffu, i4m.y, src);
            const int   ic = __shfl_sync(0xffffffffu, i4m.z, src);
            const int   id = __shfl_sync(0xffffffffu, i4m.w, src);

            const int c4 = (lid & 15) * 4;
            const int f4 = lid & 15;

            const float4 a  = __ldg((const float4*)(g_xt + ia) + f4);
            const float4 bq = __ldg((const float4*)(g_xt + ib) + f4);
            const float4 cq = __ldg((const float4*)(g_xt + ic) + f4);
            const float4 dq = __ldg((const float4*)(g_xt + id) + f4);

            float v0 = wx*a.x + wy*bq.x + wz*cq.x + ww*dq.x;
            float v1 = wx*a.y + wy*bq.y + wz*cq.y + ww*dq.y;
            float v2 = wx*a.z + wy*bq.z + wz*cq.z + ww*dq.z;
            float v3 = wx*a.w + wy*bq.w + wz*cq.w + ww*dq.w;

            __half2 h01 = __floats2half2_rn(v0, v1);   // lo = v0
            __half2 h23 = __floats2half2_rn(v2, v3);

            const int row = wid * 16 + it * 2 + (lid >> 4); // warp-private A row
            *(uint2*)(a_s + row * LDA + c4) =
                make_uint2(*(uint32_t*)&h01, *(uint32_t*)&h23);
        }

        asm volatile("cp.async.wait_group 0;" ::: "memory");
        __syncthreads();   // the ONE barrier per k

        // ---- GEMM: acc[16-row band][4 n-tiles] over this k's 64 channels ----
        {
            const __half* w_k  = (const __half*)(sm + SM_W + (k & 1) * W_BUF);
            const __half* arow = a_s + wid * 16 * LDA;
            #pragma unroll
            for (int kt = 0; kt < 4; ++kt) {
                wmma::fragment<wmma::matrix_a, 16, 16, 16, __half,
                               wmma::row_major> fa;
                wmma::load_matrix_sync(fa, arow + kt * 16, LDA);
                #pragma unroll
                for (int nt = 0; nt < 4; ++nt) {
                    wmma::fragment<wmma::matrix_b, 16, 16, 16, __half,
                                   wmma::row_major> fb;
                    wmma::load_matrix_sync(fb, w_k + kt * 16 * LDB + nt * 16, LDB);
                    wmma::mma_sync(acc[nt], fa, fb, acc[nt]);
                }
            }
        }
    }

    // ---- Epilogue: acc -> fp32 smem [128][LDE] -> transposed coalesced STG ----
    __syncthreads();                       // all warps done with A/W smem
    {
        float* smf = (float*)sm;           // reuse (34816 <= 36864)
        #pragma unroll
        for (int nt = 0; nt < 4; ++nt)
            wmma::store_matrix_sync(smf + wid * 16 * LDE + nt * 16, acc[nt],
                                    LDE, wmma::mem_row_major);
    }
    __syncthreads();
    {
        const float* smf = (const float*)sm;
        const int oc_g = tid >> 7;                    // 0/1
        const int pxe  = tid & 127;
        const size_t hw_out = (size_t)ho * WO + wo0 + pxe;
        #pragma unroll
        for (int o2 = 0; o2 < 32; ++o2) {
            const int oc = oc_g * 32 + o2;
            out[(size_t)(b * COUT + oc) * HW_ + hw_out] =
                smf[pxe * LDE + oc] + __ldg(bias + oc);
        }
    }
}

// ---------------------------------------------------------------------------
extern "C" void kernel_launch(void* const* d_in, const int* in_sizes, int n_in,
                              void* d_out, int out_size)
{
    const float* x      = (const float*)d_in[0];
    const float* offset = (const float*)d_in[1];
    const float* weight = (const float*)d_in[2];
    const float* bias   = (const float*)d_in[3];
    float* out = (float*)d_out;

    cudaFuncSetAttribute(deform_main,
                         cudaFuncAttributeMaxDynamicSharedMemorySize, SM_TOTAL);

    prep<<<8192 + (KK * C_ * COUT + 255) / 256, 256>>>(x, weight);
    deform_main<<<NPIX / TPX, THREADS, SM_TOTAL>>>(offset, bias, out);
}

// round 13
// speedup vs baseline: 6.6772x; 1.3863x over previous
#include <cuda_runtime.h>
#include <cuda_fp16.h>
#include <mma.h>
#include <cstdint>

using namespace nvcuda;

// Problem constants (DeformConvPack_39187281609181)
#define B_   4
#define C_   64
#define H_   128
#define W_   256
#define HW_  (H_ * W_)      // 32768
#define COUT 64
#define KK   9
#define HO   128
#define WO   256
#define NPIX (B_ * HO * WO) // 131072

#define TPX     128
#define THREADS 256

// smem layout (bytes)
#define LDA 72                             // A leading dim (144B rows)
#define LDB 72
#define A_BYTES (TPX * LDA * 2)            // 18432
#define W_BUF   (C_ * LDB * 2)             // 9216 per buffer
#define SM_A    0
#define SM_W    (SM_A + A_BYTES)           // 18432 ; two buffers
#define SM_TOTAL (SM_W + 2 * W_BUF)        // 36864
#define LDE 68                             // epilogue fp32 ldm (34816 <= 36864)

// Scratch (allocation-free)
__device__ __half g_xt[(size_t)B_ * HW_ * C_];   // x as NHWC fp16
__device__ __half g_wf[KK * C_ * COUT];          // weight fp16, [k][c][oc]

__device__ __forceinline__ uint32_t smem_u32(const void* p) {
    uint32_t a;
    asm("{ .reg .u64 t; cvta.to.shared.u64 t, %1; cvt.u32.u64 %0, t; }"
        : "=r"(a) : "l"(p));
    return a;
}
__device__ __forceinline__ void cp_async16(uint32_t dst, const void* src) {
    asm volatile("cp.async.ca.shared.global [%0], [%1], 16;"
                 :: "r"(dst), "l"(src) : "memory");
}

// ---------------------------------------------------------------------------
// Merged prep: blocks [0,8192) transpose x NCHW->NHWC fp16; rest convert W
__global__ void prep(const float* __restrict__ x, const float* __restrict__ w)
{
    if (blockIdx.x < 8192) {
        __shared__ float tile[32][33];
        const int bi  = blockIdx.x;
        const int b   = bi >> 11;
        const int c0  = ((bi >> 10) & 1) * 32;
        const int hw0 = (bi & 1023) * 32;
        const int tx  = threadIdx.x & 31;
        const int ty  = threadIdx.x >> 5;

        const float* xb = x + (size_t)b * C_ * HW_;
        #pragma unroll
        for (int i = 0; i < 32; i += 8)
            tile[ty + i][tx] = xb[(size_t)(c0 + ty + i) * HW_ + hw0 + tx];
        __syncthreads();

        __half* dst = g_xt + (size_t)b * HW_ * C_;
        const int c2 = threadIdx.x & 15;      // c pair
        const int rb = threadIdx.x >> 4;      // row base 0..15
        #pragma unroll
        for (int i = 0; i < 32; i += 16) {
            const int row = rb + i;
            __half2 v = __floats2half2_rn(tile[2 * c2][row], tile[2 * c2 + 1][row]);
            *(__half2*)(dst + (size_t)(hw0 + row) * C_ + c0 + 2 * c2) = v;
        }
    } else {
        // weight (Cout,Cin,3,3) -> fp16 [k][c][oc]
        const int t = (blockIdx.x - 8192) * 256 + threadIdx.x;   // 0..36863
        if (t < KK * C_ * COUT) {
            const int k  = t >> 12;
            const int c  = (t >> 6) & 63;
            const int oc = t & 63;
            g_wf[t] = __float2half(w[oc * (C_ * KK) + c * KK + k]);
        }
    }
}

// ---------------------------------------------------------------------------
__global__ void __launch_bounds__(THREADS, 3)
deform_main(const float* __restrict__ offset,
            const float* __restrict__ bias,
            float* __restrict__ out)
{
    extern __shared__ char sm[];
    __half*        a_s = (__half*)(sm + SM_A);
    const uint32_t smb = smem_u32(sm);

    const int tid = threadIdx.x;
    const int wid = tid >> 5;
    const int lid = tid & 31;

    const int p0  = blockIdx.x * TPX;
    const int b   = p0 >> 15;
    const int ho  = (p0 & 32767) >> 8;
    const int wo0 = p0 & 255;

    // Accumulators: warp wid owns px rows [16*wid, 16*wid+16), all 64 oc
    wmma::fragment<wmma::accumulator, 16, 16, 16, float> acc[4];
    #pragma unroll
    for (int n = 0; n < 4; ++n) wmma::fill_fragment(acc[n], 0.0f);

    #pragma unroll 1
    for (int k = 0; k < KK; ++k) {
        // ---- stage W(k) -> buf k&1 via cp.async (warp: 8 c-rows of 128B) ----
        {
            const uint32_t wb = smb + SM_W + (k & 1) * W_BUF;
            const int c   = wid * 8 + (lid >> 2);
            const __half* src = g_wf + k * (C_ * COUT) + c * COUT;
            #pragma unroll
            for (int j = 0; j < 2; ++j) {
                const int seg = (lid & 3) * 2 + j;          // 0..7, 16B each
                cp_async16(wb + c * 144 + seg * 16, src + seg * 8);
            }
            asm volatile("cp.async.commit_group;" ::: "memory");
        }

        // ---- warp-local bilinear meta for pixel 16*wid + (lid&15) ----
        float4 w4m; int4 i4m;
        {
            const int pxl = lid & 15;
            const int wo  = wo0 + wid * 16 + pxl;
            const size_t ob = (((size_t)b * (2 * KK) + 2 * k) * HO + ho) * WO + wo;
            const float dy = __ldg(offset + ob);
            const float dx = __ldg(offset + ob + (size_t)HO * WO);

            const int ky = k / 3, kx = k - 3 * ky;
            const float py = (float)(ho - 1 + ky) + dy;
            const float px = (float)(wo - 1 + kx) + dx;
            const float y0f = floorf(py), x0f = floorf(px);
            const float ly = py - y0f,  lx = px - x0f;
            const int y0 = (int)y0f, x0 = (int)x0f;
            const int y1 = y0 + 1,   x1 = x0 + 1;

            const float vy0 = (y0 >= 0 && y0 < H_) ? 1.0f : 0.0f;
            const float vy1 = (y1 >= 0 && y1 < H_) ? 1.0f : 0.0f;
            const float vx0 = (x0 >= 0 && x0 < W_) ? 1.0f : 0.0f;
            const float vx1 = (x1 >= 0 && x1 < W_) ? 1.0f : 0.0f;

            w4m.x = (1.0f - ly) * (1.0f - lx) * vy0 * vx0;
            w4m.y = (1.0f - ly) * lx          * vy0 * vx1;
            w4m.z = ly          * (1.0f - lx) * vy1 * vx0;
            w4m.w = ly          * lx          * vy1 * vx1;

            const int y0c = min(max(y0, 0), H_ - 1);
            const int y1c = min(max(y1, 0), H_ - 1);
            const int x0c = min(max(x0, 0), W_ - 1);
            const int x1c = min(max(x1, 0), W_ - 1);

            const int base = b * HW_;
            i4m.x = (base + y0c * W_ + x0c) * C_;
            i4m.y = (base + y0c * W_ + x1c) * C_;
            i4m.z = (base + y1c * W_ + x0c) * C_;
            i4m.w = (base + y1c * W_ + x1c) * C_;
        }

        // ---- gather: 4 iters x 4 pixels; lane covers 8 channels (16B) ----
        #pragma unroll
        for (int it = 0; it < 4; ++it) {
            const int src = it * 4 + (lid >> 3);            // meta source lane
            const float wx = __shfl_sync(0xffffffffu, w4m.x, src);
            const float wy = __shfl_sync(0xffffffffu, w4m.y, src);
            const float wz = __shfl_sync(0xffffffffu, w4m.z, src);
            const float ww = __shfl_sync(0xffffffffu, w4m.w, src);
            const int   ia = __shfl_sync(0xffffffffu, i4m.x, src);
            const int   ib = __shfl_sync(0xffffffffu, i4m.y, src);
            const int   ic = __shfl_sync(0xffffffffu, i4m.z, src);
            const int   id = __shfl_sync(0xffffffffu, i4m.w, src);

            const __half2 wx2 = __float2half2_rn(wx);
            const __half2 wy2 = __float2half2_rn(wy);
            const __half2 wz2 = __float2half2_rn(wz);
            const __half2 ww2 = __float2half2_rn(ww);

            const int g8 = lid & 7;                         // 16B chunk in row
            const uint4 ua = __ldg((const uint4*)(g_xt + ia) + g8);
            const uint4 ub = __ldg((const uint4*)(g_xt + ib) + g8);
            const uint4 uc = __ldg((const uint4*)(g_xt + ic) + g8);
            const uint4 ud = __ldg((const uint4*)(g_xt + id) + g8);
            const __half2* ha = (const __half2*)&ua;
            const __half2* hb = (const __half2*)&ub;
            const __half2* hc = (const __half2*)&uc;
            const __half2* hd = (const __half2*)&ud;

            uint4 res;
            __half2* rv = (__half2*)&res;
            #pragma unroll
            for (int j = 0; j < 4; ++j) {
                __half2 v = __hmul2(wx2, ha[j]);
                v = __hfma2(wy2, hb[j], v);
                v = __hfma2(wz2, hc[j], v);
                v = __hfma2(ww2, hd[j], v);
                rv[j] = v;
            }

            const int row = wid * 16 + it * 4 + (lid >> 3); // warp-private A row
            *(uint4*)(a_s + row * LDA + g8 * 8) = res;
        }

        asm volatile("cp.async.wait_group 0;" ::: "memory");
        __syncthreads();   // the ONE barrier per k

        // ---- GEMM: acc[16-row band][4 n-tiles] over this k's 64 channels ----
        {
            const __half* w_k  = (const __half*)(sm + SM_W + (k & 1) * W_BUF);
            const __half* arow = a_s + wid * 16 * LDA;
            #pragma unroll
            for (int kt = 0; kt < 4; ++kt) {
                wmma::fragment<wmma::matrix_a, 16, 16, 16, __half,
                               wmma::row_major> fa;
                wmma::load_matrix_sync(fa, arow + kt * 16, LDA);
                #pragma unroll
                for (int nt = 0; nt < 4; ++nt) {
                    wmma::fragment<wmma::matrix_b, 16, 16, 16, __half,
                                   wmma::row_major> fb;
                    wmma::load_matrix_sync(fb, w_k + kt * 16 * LDB + nt * 16, LDB);
                    wmma::mma_sync(acc[nt], fa, fb, acc[nt]);
                }
            }
        }
    }

    // ---- Epilogue: acc -> fp32 smem [128][LDE] -> transposed coalesced STG ----
    __syncthreads();                       // all warps done with A/W smem
    {
        float* smf = (float*)sm;           // reuse (34816 <= 36864)
        #pragma unroll
        for (int nt = 0; nt < 4; ++nt)
            wmma::store_matrix_sync(smf + wid * 16 * LDE + nt * 16, acc[nt],
                                    LDE, wmma::mem_row_major);
    }
    __syncthreads();
    {
        const float* smf = (const float*)sm;
        const int oc_g = tid >> 7;                    // 0/1
        const int pxe  = tid & 127;
        const size_t hw_out = (size_t)ho * WO + wo0 + pxe;
        #pragma unroll
        for (int o2 = 0; o2 < 32; ++o2) {
            const int oc = oc_g * 32 + o2;
            out[(size_t)(b * COUT + oc) * HW_ + hw_out] =
                smf[pxe * LDE + oc] + __ldg(bias + oc);
        }
    }
}

// ---------------------------------------------------------------------------
extern "C" void kernel_launch(void* const* d_in, const int* in_sizes, int n_in,
                              void* d_out, int out_size)
{
    const float* x      = (const float*)d_in[0];
    const float* offset = (const float*)d_in[1];
    const float* weight = (const float*)d_in[2];
    const float* bias   = (const float*)d_in[3];
    float* out = (float*)d_out;

    cudaFuncSetAttribute(deform_main,
                         cudaFuncAttributeMaxDynamicSharedMemorySize, SM_TOTAL);

    prep<<<8192 + (KK * C_ * COUT + 255) / 256, 256>>>(x, weight);
    deform_main<<<NPIX / TPX, THREADS, SM_TOTAL>>>(offset, bias, out);
}